// round 16
// baseline (speedup 1.0000x reference)
#include <cuda_runtime.h>
#include <math.h>
#include <stdint.h>

#define FULL 0xFFFFFFFFu

// monotone float->u32 key, branchless
__device__ __forceinline__ unsigned f2key(float f) {
    unsigned b = __float_as_uint(f);
    return b ^ (0x80000000u | (unsigned)((int)b >> 31));
}
__device__ __forceinline__ float key2f(unsigned k) {
    unsigned b = (k & 0x80000000u) ? (k ^ 0x80000000u) : ~k;
    return __uint_as_float(b);
}

#define CE(i, j) { unsigned a_ = s[i], b_ = s[j]; s[i] = umax(a_, b_); s[j] = umin(a_, b_); }

__global__ __launch_bounds__(128)
void topk_route_kernel(const float* __restrict__ logits,
                       const float* __restrict__ bias,
                       float* __restrict__ out, int T)
{
    const int lane = threadIdx.x & 31;
    const int warp = threadIdx.x >> 5;
    const int t = blockIdx.x * 4 + warp;
    if (t >= T) return;

    const unsigned lmlt = (1u << lane) - 1u;   // lanemask_lt

    // lane l owns experts [8l, 8l+8); all 8 are in group l>>2
    const float* lg = logits + (size_t)t * 256 + lane * 8;
    float4 x0 = *(const float4*)lg;
    float4 x1 = *(const float4*)(lg + 4);

    // passthrough logits immediately
    float* lo = out + (size_t)T * 16 + (size_t)t * 256 + lane * 8;
    *(float4*)lo = x0;
    *(float4*)(lo + 4) = x1;

    const float4* bp = (const float4*)(bias + lane * 8);
    float4 b0 = __ldg(bp), b1 = __ldg(bp + 1);

    float xx[8] = {x0.x, x0.y, x0.z, x0.w, x1.x, x1.y, x1.z, x1.w};
    float bb[8] = {b0.x, b0.y, b0.z, b0.w, b1.x, b1.y, b1.z, b1.w};

    // sigmoid (precise expf + IEEE div: selection ordering is bit-sensitive;
    // cheaper variants risk id flips worth ~2e-3 rel_err each) -> monotone keys
    unsigned orig[8], s[8];
    #pragma unroll
    for (int i = 0; i < 8; i++) {
        float si = 1.0f / (1.0f + expf(-xx[i]));
        orig[i] = f2key(si + bb[i]);
        s[i] = orig[i];
    }

    // per-lane descending sort (Batcher odd-even, 19 comparators)
    CE(0,1) CE(2,3) CE(4,5) CE(6,7)
    CE(0,2) CE(1,3) CE(4,6) CE(5,7)
    CE(1,2) CE(5,6)
    CE(0,4) CE(1,5) CE(2,6) CE(3,7)
    CE(2,4) CE(3,5)
    CE(1,2) CE(3,4) CE(5,6)

    // group score = top2 sum (per-lane top2 free from sort: s[0], s[1])
    unsigned m1 = s[0], m2 = s[1];
    #pragma unroll
    for (int off = 1; off <= 2; off <<= 1) {
        unsigned o1 = __shfl_xor_sync(FULL, m1, off);
        unsigned o2 = __shfl_xor_sync(FULL, m2, off);
        unsigned l2 = umin(m1, o1);
        m1 = umax(m1, o1);
        m2 = umax(l2, umax(m2, o2));
    }
    float gs = key2f(m1) + key2f(m2);   // identical across each quad

    // group rank via two ballots (8x8 comparison matrix, exact jax ties)
    const int grp = lane >> 2;
    const int f1 = lane & 7;
    const int f2 = f1 ^ 4;
    float gf1 = __shfl_sync(FULL, gs, f1 * 4);
    float gf2 = __shfl_sync(FULL, gs, f2 * 4);
    bool p1 = (gf1 > gs) || (gf1 == gs && f1 < grp);
    bool p2 = (gf2 > gs) || (gf2 == gs && f2 < grp);
    unsigned bq1 = __ballot_sync(FULL, p1);
    unsigned bq2 = __ballot_sync(FULL, p2);
    int rank = __popc((bq1 >> (4 * grp)) & 0xF) + __popc((bq2 >> (4 * grp)) & 0xF);
    bool sel = rank < 4;   // top-4 groups

    // mask unselected groups to key(0.0f)
    #pragma unroll
    for (int i = 0; i < 8; i++) s[i] = sel ? s[i] : 0x80000000u;

    // ---- 8 extraction rounds with SPECULATIVE next-max -------------------
    // Next round's max = max over lanes of (winner ? s[1] : s[0]).
    // spec = redux(eq ? s[1] : s[0]) is exact when the ballot has ONE winner;
    // with a multi-lane tie at kmax the true next max is kmax itself (another
    // tied lane keeps it) -> fixup select. This moves the REDUX off the
    // serial chain (issued parallel to the ballot).
    // brec init 1: lanes >= 8 resolve to a valid gidx (in-bounds bias gather).
    unsigned krec = 0, brec = 1;
    unsigned kmax = __reduce_max_sync(FULL, s[0]);
    #pragma unroll
    for (int r = 0; r < 8; r++) {
        bool eq = (s[0] == kmax);
        unsigned bal = __ballot_sync(FULL, eq);
        if (lane == r) { krec = kmax; brec = bal; }
        if (r < 7) {
            unsigned spec = __reduce_max_sync(FULL, eq ? s[1] : s[0]);
            bool p = eq && ((bal & lmlt) == 0u);   // lowest-lane winner shifts
            #pragma unroll
            for (int i = 0; i < 7 - r; i++) s[i] = p ? s[i + 1] : s[i];
            kmax = (__popc(bal) > 1) ? kmax : spec;
        }
    }
    int wrec = __ffs((int)brec) - 1;

    // index recovery: bitmask of matches in lane wrec's orig[], first = lowest
    unsigned mmask = 0;
    #pragma unroll
    for (int i = 0; i < 8; i++) {
        unsigned gk = __shfl_sync(FULL, orig[i], wrec);
        mmask |= (unsigned)(gk == krec) << i;
    }
    int pos = __ffs((int)(mmask | 0x80u)) - 1;   // guard keeps pos in [0,7]
    int gidx = (wrec << 3) + pos;

    // weight = unbiased score = biased - bias ; normalize (fast div ok); scale
    float w = key2f(krec) - __ldg(bias + gidx);
    float sum = w;
    sum += __shfl_xor_sync(FULL, sum, 1);
    sum += __shfl_xor_sync(FULL, sum, 2);
    sum += __shfl_xor_sync(FULL, sum, 4);
    float wn = __fdividef(w, sum) * 2.5f;

    if (lane < 8) {
        out[(size_t)t * 8 + lane] = wn;
        out[(size_t)T * 8 + (size_t)t * 8 + lane] = (float)gidx;
    }
}

extern "C" void kernel_launch(void* const* d_in, const int* in_sizes, int n_in,
                              void* d_out, int out_size)
{
    // inputs: hidden_states (unused), router_logits [T,256], correction_bias [256]
    const float* logits = (const float*)d_in[1];
    const float* bias   = (const float*)d_in[2];
    float* out = (float*)d_out;

    int T = in_sizes[1] / 256;
    int blocks = (T + 3) / 4;              // 1 token per warp, 4 warps per block
    topk_route_kernel<<<blocks, 128>>>(logits, bias, out, T);
}

// round 17
// speedup vs baseline: 1.0367x; 1.0367x over previous
#include <cuda_runtime.h>
#include <math.h>
#include <stdint.h>

#define FULL 0xFFFFFFFFu

// monotone float->u32 key, branchless
__device__ __forceinline__ unsigned f2key(float f) {
    unsigned b = __float_as_uint(f);
    return b ^ (0x80000000u | (unsigned)((int)b >> 31));
}
__device__ __forceinline__ float key2f(unsigned k) {
    unsigned b = (k & 0x80000000u) ? (k ^ 0x80000000u) : ~k;
    return __uint_as_float(b);
}

#define CE(i, j) { unsigned a_ = s[i], b_ = s[j]; s[i] = umax(a_, b_); s[j] = umin(a_, b_); }

__global__ __launch_bounds__(128)
void topk_route_kernel(const float* __restrict__ logits,
                       const float* __restrict__ bias,
                       float* __restrict__ out, int T)
{
    const int lane = threadIdx.x & 31;
    const int warp = threadIdx.x >> 5;
    const int t = blockIdx.x * 4 + warp;
    if (t >= T) return;

    const unsigned lmlt = (1u << lane) - 1u;   // lanemask_lt

    // lane l owns experts [8l, 8l+8); all 8 are in group l>>2
    const float* lg = logits + (size_t)t * 256 + lane * 8;
    float4 x0 = *(const float4*)lg;
    float4 x1 = *(const float4*)(lg + 4);

    // passthrough logits immediately
    float* lo = out + (size_t)T * 16 + (size_t)t * 256 + lane * 8;
    *(float4*)lo = x0;
    *(float4*)(lo + 4) = x1;

    const float4* bp = (const float4*)(bias + lane * 8);
    float4 b0 = __ldg(bp), b1 = __ldg(bp + 1);

    float xx[8] = {x0.x, x0.y, x0.z, x0.w, x1.x, x1.y, x1.z, x1.w};
    float bb[8] = {b0.x, b0.y, b0.z, b0.w, b1.x, b1.y, b1.z, b1.w};

    // sigmoid (precise expf + IEEE div: selection ordering is bit-sensitive;
    // cheaper variants risk id flips worth ~2e-3 rel_err each) -> monotone keys
    unsigned orig[8], s[8];
    #pragma unroll
    for (int i = 0; i < 8; i++) {
        float si = 1.0f / (1.0f + expf(-xx[i]));
        orig[i] = f2key(si + bb[i]);
        s[i] = orig[i];
    }

    // per-lane descending sort (Batcher odd-even, 19 comparators)
    CE(0,1) CE(2,3) CE(4,5) CE(6,7)
    CE(0,2) CE(1,3) CE(4,6) CE(5,7)
    CE(1,2) CE(5,6)
    CE(0,4) CE(1,5) CE(2,6) CE(3,7)
    CE(2,4) CE(3,5)
    CE(1,2) CE(3,4) CE(5,6)

    // group score = top2 sum (per-lane top2 free from sort: s[0], s[1])
    unsigned m1 = s[0], m2 = s[1];
    #pragma unroll
    for (int off = 1; off <= 2; off <<= 1) {
        unsigned o1 = __shfl_xor_sync(FULL, m1, off);
        unsigned o2 = __shfl_xor_sync(FULL, m2, off);
        unsigned l2 = umin(m1, o1);
        m1 = umax(m1, o1);
        m2 = umax(l2, umax(m2, o2));
    }
    float gs = key2f(m1) + key2f(m2);   // identical across each quad

    // group rank via two ballots (8x8 comparison matrix, exact jax ties)
    const int grp = lane >> 2;
    const int f1 = lane & 7;
    const int f2 = f1 ^ 4;
    float gf1 = __shfl_sync(FULL, gs, f1 * 4);
    float gf2 = __shfl_sync(FULL, gs, f2 * 4);
    bool p1 = (gf1 > gs) || (gf1 == gs && f1 < grp);
    bool p2 = (gf2 > gs) || (gf2 == gs && f2 < grp);
    unsigned bq1 = __ballot_sync(FULL, p1);
    unsigned bq2 = __ballot_sync(FULL, p2);
    int rank = __popc((bq1 >> (4 * grp)) & 0xF) + __popc((bq2 >> (4 * grp)) & 0xF);
    bool sel = rank < 4;   // top-4 groups

    // mask unselected groups to key(0.0f)
    #pragma unroll
    for (int i = 0; i < 8; i++) s[i] = sel ? s[i] : 0x80000000u;

    // 8 extraction rounds; triangular shift (round r needs depth <= 7-r after).
    // brec init 1: lanes >= 8 resolve to a valid gidx (in-bounds bias gather).
    unsigned krec = 0, brec = 1;
    #pragma unroll
    for (int r = 0; r < 8; r++) {
        unsigned kmax = __reduce_max_sync(FULL, s[0]);
        bool eq = (s[0] == kmax);
        unsigned bal = __ballot_sync(FULL, eq);
        if (lane == r) { krec = kmax; brec = bal; }
        if (r < 7) {
            bool p = eq && ((bal & lmlt) == 0u);   // lowest-lane winner shifts
            #pragma unroll
            for (int i = 0; i < 7 - r; i++) s[i] = p ? s[i + 1] : s[i];
        }
    }
    int wrec = __ffs((int)brec) - 1;

    // index recovery: bitmask of matches in lane wrec's orig[], first = lowest
    unsigned mmask = 0;
    #pragma unroll
    for (int i = 0; i < 8; i++) {
        unsigned gk = __shfl_sync(FULL, orig[i], wrec);
        mmask |= (unsigned)(gk == krec) << i;
    }
    int pos = __ffs((int)(mmask | 0x80u)) - 1;   // guard keeps pos in [0,7]
    int gidx = (wrec << 3) + pos;

    // weight = unbiased score = biased - bias ; normalize (fast div ok); scale
    float w = key2f(krec) - __ldg(bias + gidx);
    float sum = w;
    sum += __shfl_xor_sync(FULL, sum, 1);
    sum += __shfl_xor_sync(FULL, sum, 2);
    sum += __shfl_xor_sync(FULL, sum, 4);
    float wn = __fdividef(w, sum) * 2.5f;

    if (lane < 8) {
        out[(size_t)t * 8 + lane] = wn;
        out[(size_t)T * 8 + (size_t)t * 8 + lane] = (float)gidx;
    }
}

extern "C" void kernel_launch(void* const* d_in, const int* in_sizes, int n_in,
                              void* d_out, int out_size)
{
    // inputs: hidden_states (unused), router_logits [T,256], correction_bias [256]
    const float* logits = (const float*)d_in[1];
    const float* bias   = (const float*)d_in[2];
    float* out = (float*)d_out;

    int T = in_sizes[1] / 256;
    int blocks = (T + 3) / 4;              // 1 token per warp, 4 warps per block
    topk_route_kernel<<<blocks, 128>>>(logits, bias, out, T);
}